// round 10
// baseline (speedup 1.0000x reference)
#include <cuda_runtime.h>

#define NN   8192
#define IND  128
#define OUTD 64
#define HH   4
#define HO   (HH*OUTD)   // 256
#define NW   (NN/32)     // 256 bitmask words per adjacency row
#define MSPLIT 8
#define MRANGE (NN/MSPLIT)   // 1024 m's per k_gat block

// ---------------- device scratch (static: no allocations allowed) ----------
__device__ float    g_h2[HH*NN*OUTD];       // 8 MB  h in MMA B-fragment order
__device__ unsigned g_bits[NN*NW];          // 8 MB  bit-packed adjacency
__device__ float    g_ei[HH*NN];            // row (source) scores
__device__ float    g_A [HH*NN];            // exp(ei)
__device__ float    g_B [HH*NN];            // exp(0.2*ei)
__device__ float    g_ej[HH*NN];            // col (target) scores
__device__ float    g_u [HH*NN];            // exp(ej)
__device__ float    g_v [HH*NN];            // exp(0.2*ej)
__device__ float    g_pnm[(size_t)MSPLIT*NN*HO];  // 64 MB partial numerators
__device__ float    g_pdn[MSPLIT*HH*NN];          // 1 MB  partial denominators
__device__ float    g_pre[NN*HO];           // 8 MB  pre-BN output
__device__ float    g_psum[256*HO];
__device__ float    g_psq [256*HO];
__device__ float    g_scale[HO];
__device__ float    g_shift[HO];

__device__ __forceinline__ unsigned to_tf32(float x) {
    unsigned q;
    asm("cvt.rna.tf32.f32 %0, %1;" : "=r"(q) : "f"(x));
    return q;
}

#define MMA_TF32(C, A, b0, b1)                                          \
    asm("mma.sync.aligned.m16n8k8.row.col.f32.tf32.tf32.f32 "           \
        "{%0,%1,%2,%3},{%4,%5,%6,%7},{%8,%9},{%0,%1,%2,%3};"            \
        : "+f"((C)[0]), "+f"((C)[1]), "+f"((C)[2]), "+f"((C)[3])        \
        : "r"((A)[0]), "r"((A)[1]), "r"((A)[2]), "r"((A)[3]),           \
          "r"(b0), "r"(b1))

// ---------------- K0: pack adjacency into bitmask --------------------------
__global__ void k_pack(const int* __restrict__ adj) {
    int tid = blockIdx.x * 256 + threadIdx.x;
    int v = adj[tid];
    unsigned m = __ballot_sync(0xffffffffu, v != 0);
    if ((threadIdx.x & 31) == 0) g_bits[tid >> 5] = m;
}

// ---------------- K1: h = x @ W, fused scores/exp, fragment-order output ----
// block 256, tile = 32 rows of one head.
__global__ void __launch_bounds__(256) k_feat(const float* __restrict__ x,
                                              const float* __restrict__ W,
                                              const float* __restrict__ ai,
                                              const float* __restrict__ aj) {
    __shared__ float xs[32*IND];      // 16 KB
    __shared__ float Ws[IND*OUTD];    // 32 KB
    int h  = blockIdx.y;
    int n0 = blockIdx.x * 32;
    int t  = threadIdx.x;

    const float4* xsrc = (const float4*)(x + (size_t)n0 * IND);
    float4* xd = (float4*)xs;
#pragma unroll
    for (int k = 0; k < 4; k++) xd[t + k*256] = xsrc[t + k*256];
    const float4* wsrc = (const float4*)(W + (size_t)h * IND * OUTD);
    float4* wd = (float4*)Ws;
#pragma unroll
    for (int k = 0; k < 8; k++) wd[t + k*256] = wsrc[t + k*256];
    __syncthreads();

    int o2 = t & 31;        // output pair: cols 2*o2, 2*o2+1 (also lane id)
    int rg = t >> 5;        // row group: rows rg*4 .. rg*4+3
    float2 acc[4];
#pragma unroll
    for (int r = 0; r < 4; r++) { acc[r].x = 0.f; acc[r].y = 0.f; }

#pragma unroll 8
    for (int i = 0; i < IND; i++) {
        float2 wv = *(const float2*)&Ws[i*OUTD + o2*2];
#pragma unroll
        for (int r = 0; r < 4; r++) {
            float xv = xs[(rg*4 + r)*IND + i];
            acc[r].x += xv * wv.x;
            acc[r].y += xv * wv.y;
        }
    }

    // ---- fused attention scores: si = h.a_i, sj = h.a_j (fp32, pre-round) ----
    float2 aiv = *(const float2*)&ai[h*OUTD + 2*o2];
    float2 ajv = *(const float2*)&aj[h*OUTD + 2*o2];
    float si[4], sj[4];
#pragma unroll
    for (int r = 0; r < 4; r++) {
        si[r] = acc[r].x*aiv.x + acc[r].y*aiv.y;
        sj[r] = acc[r].x*ajv.x + acc[r].y*ajv.y;
    }
#pragma unroll
    for (int off = 16; off; off >>= 1) {
#pragma unroll
        for (int r = 0; r < 4; r++) {
            si[r] += __shfl_xor_sync(0xffffffffu, si[r], off);
            sj[r] += __shfl_xor_sync(0xffffffffu, sj[r], off);
        }
    }
    if (o2 < 4) {   // lane r writes row rg*4 + r
        float sI = (o2 == 0) ? si[0] : (o2 == 1) ? si[1] : (o2 == 2) ? si[2] : si[3];
        float sJ = (o2 == 0) ? sj[0] : (o2 == 1) ? sj[1] : (o2 == 2) ? sj[2] : sj[3];
        int idx = h*NN + n0 + rg*4 + o2;
        g_ei[idx] = sI;
        g_A [idx] = expf(sI);
        g_B [idx] = expf(0.2f * sI);
        g_ej[idx] = sJ;
        g_u [idx] = expf(sJ);
        g_v [idx] = expf(0.2f * sJ);
    }

    // ---- store h in MMA B-fragment order (tf32-rounded) ----
    // For m16n8k8.row.col: thread lane=(g*4+tg) needs {B[k=tg][n=g], B[k=tg+4][n=g]}
    // per (8-m chunk ch, 8-col tile o). Layout within a 32-m tile (2048 floats):
    //   idx = (ch*8 + o)*64 + (g*4 + tg)*2 + half
    int hbase = h * (NN * OUTD);
#pragma unroll
    for (int r = 0; r < 4; r++) {
        int n    = n0 + rg*4 + r;
        int mm   = n & 31;
        int ch   = mm >> 3;
        int tg2  = mm & 3;
        int half = (mm >> 2) & 1;
        int c0   = 2*o2;
        int o    = c0 >> 3;
        int g    = c0 & 7;
        int idx  = ((ch<<3) + o)*64 + (g*4 + tg2)*2 + half;
        float* dst = g_h2 + hbase + (n >> 5)*2048 + idx;
        dst[0] = __uint_as_float(to_tf32(acc[r].x));
        dst[8] = __uint_as_float(to_tf32(acc[r].y));   // col c0+1 -> g+1 -> +8
    }
}

// ---------------- K3: tensor-core masked-softmax aggregation ----------------
// grid (NN/256, HH, MSPLIT), block 256 = 8 warps. Warp w -> 32 n-rows, 64 outs.
__global__ void __launch_bounds__(256, 2) k_gat_mma() {
    __shared__ __align__(16) float hs2[2048];   // 8 KB: one 32-m tile, frag order
    __shared__ float    us[32], vs[32], es[32];
    __shared__ unsigned bws[256];

    int hh = blockIdx.y;
    int z  = blockIdx.z;
    int n0 = blockIdx.x * 256;
    int t  = threadIdx.x;
    int w    = t >> 5;
    int lane = t & 31;
    int g    = lane >> 2;   // groupID
    int tg   = lane & 3;    // thread-in-group
    int mbase = z * MRANGE;

    float nt[4], Ae[4], Be[4];
    int rbase = hh*NN + n0 + w*32 + g;
#pragma unroll
    for (int r = 0; r < 4; r++) {
        nt[r] = -g_ei[rbase + 8*r];
        Ae[r] =  g_A [rbase + 8*r];
        Be[r] =  g_B [rbase + 8*r];
    }

    float C[2][8][4];
#pragma unroll
    for (int a = 0; a < 2; a++)
#pragma unroll
        for (int o = 0; o < 8; o++)
#pragma unroll
            for (int k = 0; k < 4; k++) C[a][o][k] = 0.f;
    float den[4] = {0.f, 0.f, 0.f, 0.f};

    const float4* hsrc = (const float4*)(g_h2 + (size_t)hh*NN*OUTD);

    for (int sc = 0; sc < MRANGE/32; ++sc) {
        int m0s = mbase + sc*32;
        __syncthreads();
        // stage: straight contiguous copy (tile already in fragment order)
        {
            const float4* src = hsrc + (size_t)(m0s >> 5) * 512;
            float4* dst = (float4*)hs2;
            dst[t]       = src[t];
            dst[t + 256] = src[t + 256];
        }
        if (t < 32)       us[t]      = g_u [hh*NN + m0s + t];
        else if (t < 64)  vs[t - 32] = g_v [hh*NN + m0s + t - 32];
        else if (t < 96)  es[t - 64] = g_ej[hh*NN + m0s + t - 64];
        bws[t] = g_bits[(size_t)(n0 + t)*NW + (m0s >> 5)];
        __syncthreads();

        unsigned bwreg[4];
#pragma unroll
        for (int r = 0; r < 4; r++) bwreg[r] = bws[w*32 + g + 8*r];

#pragma unroll
        for (int ch = 0; ch < 4; ++ch) {
            int mb = ch*8;
            float u0 = us[mb+tg],   v0 = vs[mb+tg],   e0 = es[mb+tg];
            float u1 = us[mb+tg+4], v1 = vs[mb+tg+4], e1 = es[mb+tg+4];
            unsigned mk0 = 1u << (mb + tg);
            unsigned mk1 = mk0 << 4;
            unsigned A0[4], A1[4];
#pragma unroll
            for (int r = 0; r < 4; r++) {
                float p0 = (e0 >= nt[r]) ? Ae[r]*u0 : Be[r]*v0;
                p0 = (bwreg[r] & mk0) ? p0 : 0.f;
                unsigned q0 = to_tf32(p0);
                den[r] += __uint_as_float(q0);
                float p1 = (e1 >= nt[r]) ? Ae[r]*u1 : Be[r]*v1;
                p1 = (bwreg[r] & mk1) ? p1 : 0.f;
                unsigned q1 = to_tf32(p1);
                den[r] += __uint_as_float(q1);
                if (r < 2) { A0[(r&1)] = q0; A0[2 + (r&1)] = q1; }
                else       { A1[(r&1)] = q0; A1[2 + (r&1)] = q1; }
            }
            // conflict-free LDS.64 B-fragment loads
            const float2* bo = (const float2*)hs2 + ch*256 + lane;
#pragma unroll
            for (int o = 0; o < 8; o++) {
                float2 bq = bo[o*32];
                unsigned b0 = __float_as_uint(bq.x);
                unsigned b1 = __float_as_uint(bq.y);
                MMA_TF32(C[0][o], A0, b0, b1);
                MMA_TF32(C[1][o], A1, b0, b1);
            }
        }
    }

    // reduce denominators across the 4-lane k-group
#pragma unroll
    for (int r = 0; r < 4; r++) {
        den[r] += __shfl_xor_sync(0xffffffffu, den[r], 1);
        den[r] += __shfl_xor_sync(0xffffffffu, den[r], 2);
    }
    if (tg == 0) {
#pragma unroll
        for (int r = 0; r < 4; r++)
            g_pdn[((size_t)z*HH + hh)*NN + n0 + w*32 + g + 8*r] = den[r];
    }

    // write unnormalized partial numerators
    float* dst = g_pnm + ((size_t)z*NN + n0 + w*32)*HO + hh*OUTD;
#pragma unroll
    for (int tile = 0; tile < 2; tile++) {
        int rl = tile*16 + g;
        int rh = rl + 8;
#pragma unroll
        for (int o = 0; o < 8; o++) {
            int col = o*8 + 2*tg;
            *(float2*)&dst[(size_t)rl*HO + col] = make_float2(C[tile][o][0], C[tile][o][1]);
            *(float2*)&dst[(size_t)rh*HO + col] = make_float2(C[tile][o][2], C[tile][o][3]);
        }
    }
}

// ---------------- K3b: combine m-split partials ------------------------------
__global__ void k_combine() {     // grid NN, block 256
    int f = threadIdx.x;
    int n = blockIdx.x;
    float num = 0.f;
#pragma unroll
    for (int s = 0; s < MSPLIT; s++)
        num += g_pnm[((size_t)s*NN + n)*HO + f];
    int h = f >> 6;
    float den = 0.f;
#pragma unroll
    for (int s = 0; s < MSPLIT; s++)
        den += g_pdn[((size_t)s*HH + h)*NN + n];
    g_pre[(size_t)n*HO + f] = num / den;
}

// ---------------- K4: BN partial stats ---------------------------------------
__global__ void k_stats() {            // grid 256, block 256
    int f  = threadIdx.x;
    int b  = blockIdx.x;
    int r0 = b * 32;
    float s = 0.f, q = 0.f;
#pragma unroll 8
    for (int r = 0; r < 32; r++) {
        float vv = g_pre[(size_t)(r0 + r)*HO + f];
        s += vv;
        q += vv * vv;
    }
    g_psum[b*HO + f] = s;
    g_psq [b*HO + f] = q;
}

// ---------------- K5: finalize per-feature scale/shift ------------------------
__global__ void k_fin(const float* __restrict__ gamma,
                      const float* __restrict__ beta) {   // 1 block, 256 thr
    int f = threadIdx.x;
    float s = 0.f, q = 0.f;
    for (int k = 0; k < 256; k++) {
        s += g_psum[k*HO + f];
        q += g_psq [k*HO + f];
    }
    float mean = s * (1.0f / NN);
    float var  = q * (1.0f / NN) - mean * mean;
    float sc   = gamma[f] * rsqrtf(var + 1e-5f);
    g_scale[f] = sc;
    g_shift[f] = beta[f] - mean * sc;
}

// ---------------- K6: normalize + ReLU ----------------------------------------
__global__ void k_bn(float* __restrict__ out) {   // grid 8192, block 256
    int f = threadIdx.x;
    size_t idx = (size_t)blockIdx.x * HO + f;
    float v = g_pre[idx] * g_scale[f] + g_shift[f];
    out[idx] = v > 0.f ? v : 0.f;
}

// ---------------- launch -------------------------------------------------------
extern "C" void kernel_launch(void* const* d_in, const int* in_sizes, int n_in,
                              void* d_out, int out_size) {
    const float* x     = (const float*)d_in[0];   // [N, IN]
    const int*   adj   = (const int*)  d_in[1];   // [N, N]
    const float* W     = (const float*)d_in[2];   // [H, IN, OUT]
    const float* a_i   = (const float*)d_in[3];   // [H, OUT]
    const float* a_j   = (const float*)d_in[4];   // [H, OUT]
    const float* gamma = (const float*)d_in[5];   // [HO]
    const float* beta  = (const float*)d_in[6];   // [HO]
    float* out = (float*)d_out;                   // [N, HO]

    k_pack   <<< (NN/256)*NN, 256 >>>(adj);
    k_feat   <<< dim3(NN/32, HH), 256 >>>(x, W, a_i, a_j);
    k_gat_mma<<< dim3(NN/256, HH, MSPLIT), 256 >>>();
    k_combine<<< NN, 256 >>>();
    k_stats  <<< 256, 256 >>>();
    k_fin    <<< 1, 256 >>>(gamma, beta);
    k_bn     <<< NN, 256 >>>(out);
}

// round 11
// speedup vs baseline: 1.0070x; 1.0070x over previous
#include <cuda_runtime.h>

#define NN   8192
#define IND  128
#define OUTD 64
#define HH   4
#define HO   (HH*OUTD)   // 256
#define NW   (NN/32)     // 256 bitmask words per adjacency row
#define MSPLIT 8
#define MRANGE (NN/MSPLIT)   // 1024 m's per k_gat block

// ---------------- device scratch (static: no allocations allowed) ----------
__device__ float    g_h2[HH*NN*OUTD];       // 8 MB  h in MMA B-fragment order
__device__ unsigned g_bits[NN*NW];          // 8 MB  bit-packed adjacency
__device__ float    g_ei[HH*NN];            // row (source) scores
__device__ float    g_A [HH*NN];            // exp(ei)
__device__ float    g_B [HH*NN];            // exp(0.2*ei)
__device__ float    g_ej[HH*NN];            // col (target) scores
__device__ float    g_u [HH*NN];            // exp(ej)
__device__ float    g_v [HH*NN];            // exp(0.2*ej)
__device__ float    g_pnm[(size_t)MSPLIT*NN*HO];  // 64 MB partial numerators
__device__ float    g_pdn[MSPLIT*HH*NN];          // 1 MB  partial denominators
__device__ float    g_pre[NN*HO];           // 8 MB  pre-BN output
__device__ float    g_psum[256*HO];
__device__ float    g_psq [256*HO];
__device__ float    g_scale[HO];
__device__ float    g_shift[HO];

__device__ __forceinline__ unsigned to_tf32(float x) {
    unsigned q;
    asm("cvt.rna.tf32.f32 %0, %1;" : "=r"(q) : "f"(x));
    return q;
}

#define MMA_TF32(C, A, b0, b1)                                          \
    asm("mma.sync.aligned.m16n8k8.row.col.f32.tf32.tf32.f32 "           \
        "{%0,%1,%2,%3},{%4,%5,%6,%7},{%8,%9},{%0,%1,%2,%3};"            \
        : "+f"((C)[0]), "+f"((C)[1]), "+f"((C)[2]), "+f"((C)[3])        \
        : "r"((A)[0]), "r"((A)[1]), "r"((A)[2]), "r"((A)[3]),           \
          "r"(b0), "r"(b1))

// ---------------- K0: pack adjacency into bitmask --------------------------
__global__ void k_pack(const int* __restrict__ adj) {
    int tid = blockIdx.x * 256 + threadIdx.x;
    int v = adj[tid];
    unsigned m = __ballot_sync(0xffffffffu, v != 0);
    if ((threadIdx.x & 31) == 0) g_bits[tid >> 5] = m;
}

// ---------------- K1: h = x @ W, fused scores/exp, fragment-order output ----
// block 256, tile = 32 rows of one head.
__global__ void __launch_bounds__(256) k_feat(const float* __restrict__ x,
                                              const float* __restrict__ W,
                                              const float* __restrict__ ai,
                                              const float* __restrict__ aj) {
    __shared__ float xs[32*IND];      // 16 KB
    __shared__ float Ws[IND*OUTD];    // 32 KB
    int h  = blockIdx.y;
    int n0 = blockIdx.x * 32;
    int t  = threadIdx.x;

    const float4* xsrc = (const float4*)(x + (size_t)n0 * IND);
    float4* xd = (float4*)xs;
#pragma unroll
    for (int k = 0; k < 4; k++) xd[t + k*256] = xsrc[t + k*256];
    const float4* wsrc = (const float4*)(W + (size_t)h * IND * OUTD);
    float4* wd = (float4*)Ws;
#pragma unroll
    for (int k = 0; k < 8; k++) wd[t + k*256] = wsrc[t + k*256];
    __syncthreads();

    int o2 = t & 31;        // output pair: cols 2*o2, 2*o2+1 (also lane id)
    int rg = t >> 5;        // row group: rows rg*4 .. rg*4+3
    float2 acc[4];
#pragma unroll
    for (int r = 0; r < 4; r++) { acc[r].x = 0.f; acc[r].y = 0.f; }

#pragma unroll 8
    for (int i = 0; i < IND; i++) {
        float2 wv = *(const float2*)&Ws[i*OUTD + o2*2];
#pragma unroll
        for (int r = 0; r < 4; r++) {
            float xv = xs[(rg*4 + r)*IND + i];
            acc[r].x += xv * wv.x;
            acc[r].y += xv * wv.y;
        }
    }

    // ---- fused attention scores: si = h.a_i, sj = h.a_j (fp32, pre-round) ----
    float2 aiv = *(const float2*)&ai[h*OUTD + 2*o2];
    float2 ajv = *(const float2*)&aj[h*OUTD + 2*o2];
    float si[4], sj[4];
#pragma unroll
    for (int r = 0; r < 4; r++) {
        si[r] = acc[r].x*aiv.x + acc[r].y*aiv.y;
        sj[r] = acc[r].x*ajv.x + acc[r].y*ajv.y;
    }
#pragma unroll
    for (int off = 16; off; off >>= 1) {
#pragma unroll
        for (int r = 0; r < 4; r++) {
            si[r] += __shfl_xor_sync(0xffffffffu, si[r], off);
            sj[r] += __shfl_xor_sync(0xffffffffu, sj[r], off);
        }
    }
    if (o2 < 4) {   // lane r writes row rg*4 + r
        float sI = (o2 == 0) ? si[0] : (o2 == 1) ? si[1] : (o2 == 2) ? si[2] : si[3];
        float sJ = (o2 == 0) ? sj[0] : (o2 == 1) ? sj[1] : (o2 == 2) ? sj[2] : sj[3];
        int idx = h*NN + n0 + rg*4 + o2;
        g_ei[idx] = sI;
        g_A [idx] = expf(sI);
        g_B [idx] = expf(0.2f * sI);
        g_ej[idx] = sJ;
        g_u [idx] = expf(sJ);
        g_v [idx] = expf(0.2f * sJ);
    }

    // ---- store h in MMA B-fragment order (tf32-rounded) ----
    // For m16n8k8.row.col: thread lane=(g*4+tg) needs {B[k=tg][n=g], B[k=tg+4][n=g]}
    // per (8-m chunk ch, 8-col tile o). Layout within a 32-m tile (2048 floats):
    //   idx = (ch*8 + o)*64 + (g*4 + tg)*2 + half
    int hbase = h * (NN * OUTD);
#pragma unroll
    for (int r = 0; r < 4; r++) {
        int n    = n0 + rg*4 + r;
        int mm   = n & 31;
        int ch   = mm >> 3;
        int tg2  = mm & 3;
        int half = (mm >> 2) & 1;
        int c0   = 2*o2;
        int o    = c0 >> 3;
        int g    = c0 & 7;
        int idx  = ((ch<<3) + o)*64 + (g*4 + tg2)*2 + half;
        float* dst = g_h2 + hbase + (n >> 5)*2048 + idx;
        dst[0] = __uint_as_float(to_tf32(acc[r].x));
        dst[8] = __uint_as_float(to_tf32(acc[r].y));   // col c0+1 -> g+1 -> +8
    }
}

// ---------------- K3: tensor-core masked-softmax aggregation ----------------
// grid (NN/256, HH, MSPLIT), block 256 = 8 warps. Warp w -> 32 n-rows, 64 outs.
__global__ void __launch_bounds__(256, 2) k_gat_mma() {
    __shared__ __align__(16) float hs2[2048];   // 8 KB: one 32-m tile, frag order
    __shared__ float    us[32], vs[32], es[32];
    __shared__ unsigned bws[256];

    int hh = blockIdx.y;
    int z  = blockIdx.z;
    int n0 = blockIdx.x * 256;
    int t  = threadIdx.x;
    int w    = t >> 5;
    int lane = t & 31;
    int g    = lane >> 2;   // groupID
    int tg   = lane & 3;    // thread-in-group
    int mbase = z * MRANGE;

    float nt[4], Ae[4], Be[4];
    int rbase = hh*NN + n0 + w*32 + g;
#pragma unroll
    for (int r = 0; r < 4; r++) {
        nt[r] = -g_ei[rbase + 8*r];
        Ae[r] =  g_A [rbase + 8*r];
        Be[r] =  g_B [rbase + 8*r];
    }

    float C[2][8][4];
#pragma unroll
    for (int a = 0; a < 2; a++)
#pragma unroll
        for (int o = 0; o < 8; o++)
#pragma unroll
            for (int k = 0; k < 4; k++) C[a][o][k] = 0.f;
    float den[4] = {0.f, 0.f, 0.f, 0.f};

    const float4* hsrc = (const float4*)(g_h2 + (size_t)hh*NN*OUTD);

    for (int sc = 0; sc < MRANGE/32; ++sc) {
        int m0s = mbase + sc*32;
        __syncthreads();
        // stage: straight contiguous copy (tile already in fragment order)
        {
            const float4* src = hsrc + (size_t)(m0s >> 5) * 512;
            float4* dst = (float4*)hs2;
            dst[t]       = src[t];
            dst[t + 256] = src[t + 256];
        }
        if (t < 32)       us[t]      = g_u [hh*NN + m0s + t];
        else if (t < 64)  vs[t - 32] = g_v [hh*NN + m0s + t - 32];
        else if (t < 96)  es[t - 64] = g_ej[hh*NN + m0s + t - 64];
        bws[t] = g_bits[(size_t)(n0 + t)*NW + (m0s >> 5)];
        __syncthreads();

        unsigned bwreg[4];
#pragma unroll
        for (int r = 0; r < 4; r++) bwreg[r] = bws[w*32 + g + 8*r];

#pragma unroll
        for (int ch = 0; ch < 4; ++ch) {
            int mb = ch*8;
            float u0 = us[mb+tg],   v0 = vs[mb+tg],   e0 = es[mb+tg];
            float u1 = us[mb+tg+4], v1 = vs[mb+tg+4], e1 = es[mb+tg+4];
            unsigned mk0 = 1u << (mb + tg);
            unsigned mk1 = mk0 << 4;
            unsigned A0[4], A1[4];
#pragma unroll
            for (int r = 0; r < 4; r++) {
                float p0 = (e0 >= nt[r]) ? Ae[r]*u0 : Be[r]*v0;
                p0 = (bwreg[r] & mk0) ? p0 : 0.f;
                unsigned q0 = to_tf32(p0);
                den[r] += __uint_as_float(q0);
                float p1 = (e1 >= nt[r]) ? Ae[r]*u1 : Be[r]*v1;
                p1 = (bwreg[r] & mk1) ? p1 : 0.f;
                unsigned q1 = to_tf32(p1);
                den[r] += __uint_as_float(q1);
                if (r < 2) { A0[(r&1)] = q0; A0[2 + (r&1)] = q1; }
                else       { A1[(r&1)] = q0; A1[2 + (r&1)] = q1; }
            }
            // conflict-free LDS.64 B-fragment loads
            const float2* bo = (const float2*)hs2 + ch*256 + lane;
#pragma unroll
            for (int o = 0; o < 8; o++) {
                float2 bq = bo[o*32];
                unsigned b0 = __float_as_uint(bq.x);
                unsigned b1 = __float_as_uint(bq.y);
                MMA_TF32(C[0][o], A0, b0, b1);
                MMA_TF32(C[1][o], A1, b0, b1);
            }
        }
    }

    // reduce denominators across the 4-lane k-group
#pragma unroll
    for (int r = 0; r < 4; r++) {
        den[r] += __shfl_xor_sync(0xffffffffu, den[r], 1);
        den[r] += __shfl_xor_sync(0xffffffffu, den[r], 2);
    }
    if (tg == 0) {
#pragma unroll
        for (int r = 0; r < 4; r++)
            g_pdn[((size_t)z*HH + hh)*NN + n0 + w*32 + g + 8*r] = den[r];
    }

    // write unnormalized partial numerators
    float* dst = g_pnm + ((size_t)z*NN + n0 + w*32)*HO + hh*OUTD;
#pragma unroll
    for (int tile = 0; tile < 2; tile++) {
        int rl = tile*16 + g;
        int rh = rl + 8;
#pragma unroll
        for (int o = 0; o < 8; o++) {
            int col = o*8 + 2*tg;
            *(float2*)&dst[(size_t)rl*HO + col] = make_float2(C[tile][o][0], C[tile][o][1]);
            *(float2*)&dst[(size_t)rh*HO + col] = make_float2(C[tile][o][2], C[tile][o][3]);
        }
    }
}

// ---------------- K3b: combine m-split partials ------------------------------
__global__ void k_combine() {     // grid NN, block 256
    int f = threadIdx.x;
    int n = blockIdx.x;
    float num = 0.f;
#pragma unroll
    for (int s = 0; s < MSPLIT; s++)
        num += g_pnm[((size_t)s*NN + n)*HO + f];
    int h = f >> 6;
    float den = 0.f;
#pragma unroll
    for (int s = 0; s < MSPLIT; s++)
        den += g_pdn[((size_t)s*HH + h)*NN + n];
    g_pre[(size_t)n*HO + f] = num / den;
}

// ---------------- K4: BN partial stats ---------------------------------------
__global__ void k_stats() {            // grid 256, block 256
    int f  = threadIdx.x;
    int b  = blockIdx.x;
    int r0 = b * 32;
    float s = 0.f, q = 0.f;
#pragma unroll 8
    for (int r = 0; r < 32; r++) {
        float vv = g_pre[(size_t)(r0 + r)*HO + f];
        s += vv;
        q += vv * vv;
    }
    g_psum[b*HO + f] = s;
    g_psq [b*HO + f] = q;
}

// ---------------- K5: finalize per-feature scale/shift ------------------------
__global__ void k_fin(const float* __restrict__ gamma,
                      const float* __restrict__ beta) {   // 1 block, 256 thr
    int f = threadIdx.x;
    float s = 0.f, q = 0.f;
    for (int k = 0; k < 256; k++) {
        s += g_psum[k*HO + f];
        q += g_psq [k*HO + f];
    }
    float mean = s * (1.0f / NN);
    float var  = q * (1.0f / NN) - mean * mean;
    float sc   = gamma[f] * rsqrtf(var + 1e-5f);
    g_scale[f] = sc;
    g_shift[f] = beta[f] - mean * sc;
}

// ---------------- K6: normalize + ReLU ----------------------------------------
__global__ void k_bn(float* __restrict__ out) {   // grid 8192, block 256
    int f = threadIdx.x;
    size_t idx = (size_t)blockIdx.x * HO + f;
    float v = g_pre[idx] * g_scale[f] + g_shift[f];
    out[idx] = v > 0.f ? v : 0.f;
}

// ---------------- launch -------------------------------------------------------
extern "C" void kernel_launch(void* const* d_in, const int* in_sizes, int n_in,
                              void* d_out, int out_size) {
    const float* x     = (const float*)d_in[0];   // [N, IN]
    const int*   adj   = (const int*)  d_in[1];   // [N, N]
    const float* W     = (const float*)d_in[2];   // [H, IN, OUT]
    const float* a_i   = (const float*)d_in[3];   // [H, OUT]
    const float* a_j   = (const float*)d_in[4];   // [H, OUT]
    const float* gamma = (const float*)d_in[5];   // [HO]
    const float* beta  = (const float*)d_in[6];   // [HO]
    float* out = (float*)d_out;                   // [N, HO]

    k_pack   <<< (NN/256)*NN, 256 >>>(adj);
    k_feat   <<< dim3(NN/32, HH), 256 >>>(x, W, a_i, a_j);
    k_gat_mma<<< dim3(NN/256, HH, MSPLIT), 256 >>>();
    k_combine<<< NN, 256 >>>();
    k_stats  <<< 256, 256 >>>();
    k_fin    <<< 1, 256 >>>(gamma, beta);
    k_bn     <<< NN, 256 >>>(out);
}

// round 12
// speedup vs baseline: 1.0083x; 1.0013x over previous
#include <cuda_runtime.h>

#define NN   8192
#define IND  128
#define OUTD 64
#define HH   4
#define HO   (HH*OUTD)   // 256
#define NW   (NN/32)     // 256 bitmask words per adjacency row
#define MSPLIT 8
#define MRANGE (NN/MSPLIT)   // 1024 m's per k_gat block

// ---------------- device scratch (static: no allocations allowed) ----------
__device__ float    g_h2[HH*NN*OUTD];       // 8 MB  h in MMA B-fragment order
__device__ unsigned g_bits[NN*NW];          // 8 MB  bit-packed adjacency
__device__ float    g_ei[HH*NN];            // row (source) scores
__device__ float    g_A [HH*NN];            // exp(ei)
__device__ float    g_B [HH*NN];            // exp(0.2*ei)
__device__ float    g_ej[HH*NN];            // col (target) scores
__device__ float    g_u [HH*NN];            // exp(ej)
__device__ float    g_v [HH*NN];            // exp(0.2*ej)
__device__ float    g_pnm[(size_t)MSPLIT*NN*HO];  // 64 MB partial numerators
__device__ float    g_pdn[MSPLIT*HH*NN];          // 1 MB  partial denominators
__device__ float    g_pre[NN*HO];           // 8 MB  pre-BN output
__device__ float    g_psum[256*HO];
__device__ float    g_psq [256*HO];
__device__ float    g_scale[HO];
__device__ float    g_shift[HO];

__device__ __forceinline__ unsigned to_tf32(float x) {
    unsigned q;
    asm("cvt.rna.tf32.f32 %0, %1;" : "=r"(q) : "f"(x));
    return q;
}

#define MMA_TF32(C, A, b0, b1)                                          \
    asm("mma.sync.aligned.m16n8k8.row.col.f32.tf32.tf32.f32 "           \
        "{%0,%1,%2,%3},{%4,%5,%6,%7},{%8,%9},{%0,%1,%2,%3};"            \
        : "+f"((C)[0]), "+f"((C)[1]), "+f"((C)[2]), "+f"((C)[3])        \
        : "r"((A)[0]), "r"((A)[1]), "r"((A)[2]), "r"((A)[3]),           \
          "r"(b0), "r"(b1))

// ---------------- K0: pack adjacency into bitmask --------------------------
__global__ void k_pack(const int* __restrict__ adj) {
    int tid = blockIdx.x * 256 + threadIdx.x;
    int v = adj[tid];
    unsigned m = __ballot_sync(0xffffffffu, v != 0);
    if ((threadIdx.x & 31) == 0) g_bits[tid >> 5] = m;
}

// ---------------- K1: h = x @ W, fused scores/exp, fragment-order output ----
// block 256, tile = 32 rows of one head.
__global__ void __launch_bounds__(256) k_feat(const float* __restrict__ x,
                                              const float* __restrict__ W,
                                              const float* __restrict__ ai,
                                              const float* __restrict__ aj) {
    __shared__ float xs[32*IND];      // 16 KB
    __shared__ float Ws[IND*OUTD];    // 32 KB
    int h  = blockIdx.y;
    int n0 = blockIdx.x * 32;
    int t  = threadIdx.x;

    const float4* xsrc = (const float4*)(x + (size_t)n0 * IND);
    float4* xd = (float4*)xs;
#pragma unroll
    for (int k = 0; k < 4; k++) xd[t + k*256] = xsrc[t + k*256];
    const float4* wsrc = (const float4*)(W + (size_t)h * IND * OUTD);
    float4* wd = (float4*)Ws;
#pragma unroll
    for (int k = 0; k < 8; k++) wd[t + k*256] = wsrc[t + k*256];
    __syncthreads();

    int o2 = t & 31;        // output pair: cols 2*o2, 2*o2+1 (also lane id)
    int rg = t >> 5;        // row group: rows rg*4 .. rg*4+3
    float2 acc[4];
#pragma unroll
    for (int r = 0; r < 4; r++) { acc[r].x = 0.f; acc[r].y = 0.f; }

#pragma unroll 8
    for (int i = 0; i < IND; i++) {
        float2 wv = *(const float2*)&Ws[i*OUTD + o2*2];
#pragma unroll
        for (int r = 0; r < 4; r++) {
            float xv = xs[(rg*4 + r)*IND + i];
            acc[r].x += xv * wv.x;
            acc[r].y += xv * wv.y;
        }
    }

    // ---- fused attention scores: si = h.a_i, sj = h.a_j (fp32, pre-round) ----
    float2 aiv = *(const float2*)&ai[h*OUTD + 2*o2];
    float2 ajv = *(const float2*)&aj[h*OUTD + 2*o2];
    float si[4], sj[4];
#pragma unroll
    for (int r = 0; r < 4; r++) {
        si[r] = acc[r].x*aiv.x + acc[r].y*aiv.y;
        sj[r] = acc[r].x*ajv.x + acc[r].y*ajv.y;
    }
#pragma unroll
    for (int off = 16; off; off >>= 1) {
#pragma unroll
        for (int r = 0; r < 4; r++) {
            si[r] += __shfl_xor_sync(0xffffffffu, si[r], off);
            sj[r] += __shfl_xor_sync(0xffffffffu, sj[r], off);
        }
    }
    if (o2 < 4) {   // lane r writes row rg*4 + r
        float sI = (o2 == 0) ? si[0] : (o2 == 1) ? si[1] : (o2 == 2) ? si[2] : si[3];
        float sJ = (o2 == 0) ? sj[0] : (o2 == 1) ? sj[1] : (o2 == 2) ? sj[2] : sj[3];
        int idx = h*NN + n0 + rg*4 + o2;
        g_ei[idx] = sI;
        g_A [idx] = expf(sI);
        g_B [idx] = expf(0.2f * sI);
        g_ej[idx] = sJ;
        g_u [idx] = expf(sJ);
        g_v [idx] = expf(0.2f * sJ);
    }

    // ---- store h in MMA B-fragment order (tf32-rounded) ----
    // For m16n8k8.row.col: thread lane=(g*4+tg) needs {B[k=tg][n=g], B[k=tg+4][n=g]}
    // per (8-m chunk ch, 8-col tile o). Layout within a 32-m tile (2048 floats):
    //   idx = (ch*8 + o)*64 + (g*4 + tg)*2 + half
    int hbase = h * (NN * OUTD);
#pragma unroll
    for (int r = 0; r < 4; r++) {
        int n    = n0 + rg*4 + r;
        int mm   = n & 31;
        int ch   = mm >> 3;
        int tg2  = mm & 3;
        int half = (mm >> 2) & 1;
        int c0   = 2*o2;
        int o    = c0 >> 3;
        int g    = c0 & 7;
        int idx  = ((ch<<3) + o)*64 + (g*4 + tg2)*2 + half;
        float* dst = g_h2 + hbase + (n >> 5)*2048 + idx;
        dst[0] = __uint_as_float(to_tf32(acc[r].x));
        dst[8] = __uint_as_float(to_tf32(acc[r].y));   // col c0+1 -> g+1 -> +8
    }
}

// ---------------- K3: tensor-core masked-softmax aggregation ----------------
// grid (NN/256, HH, MSPLIT), block 256 = 8 warps. Warp w -> 32 n-rows, 64 outs.
__global__ void __launch_bounds__(256, 2) k_gat_mma() {
    __shared__ __align__(16) float hs2[2048];   // 8 KB: one 32-m tile, frag order
    __shared__ float    us[32], vs[32], es[32];
    __shared__ unsigned bws[256];

    int hh = blockIdx.y;
    int z  = blockIdx.z;
    int n0 = blockIdx.x * 256;
    int t  = threadIdx.x;
    int w    = t >> 5;
    int lane = t & 31;
    int g    = lane >> 2;   // groupID
    int tg   = lane & 3;    // thread-in-group
    int mbase = z * MRANGE;

    float nt[4], Ae[4], Be[4];
    int rbase = hh*NN + n0 + w*32 + g;
#pragma unroll
    for (int r = 0; r < 4; r++) {
        nt[r] = -g_ei[rbase + 8*r];
        Ae[r] =  g_A [rbase + 8*r];
        Be[r] =  g_B [rbase + 8*r];
    }

    float C[2][8][4];
#pragma unroll
    for (int a = 0; a < 2; a++)
#pragma unroll
        for (int o = 0; o < 8; o++)
#pragma unroll
            for (int k = 0; k < 4; k++) C[a][o][k] = 0.f;
    float den[4] = {0.f, 0.f, 0.f, 0.f};

    const float4* hsrc = (const float4*)(g_h2 + (size_t)hh*NN*OUTD);

    for (int sc = 0; sc < MRANGE/32; ++sc) {
        int m0s = mbase + sc*32;
        __syncthreads();
        // stage: straight contiguous copy (tile already in fragment order)
        {
            const float4* src = hsrc + (size_t)(m0s >> 5) * 512;
            float4* dst = (float4*)hs2;
            dst[t]       = src[t];
            dst[t + 256] = src[t + 256];
        }
        if (t < 32)       us[t]      = g_u [hh*NN + m0s + t];
        else if (t < 64)  vs[t - 32] = g_v [hh*NN + m0s + t - 32];
        else if (t < 96)  es[t - 64] = g_ej[hh*NN + m0s + t - 64];
        bws[t] = g_bits[(size_t)(n0 + t)*NW + (m0s >> 5)];
        __syncthreads();

        unsigned bwreg[4];
#pragma unroll
        for (int r = 0; r < 4; r++) bwreg[r] = bws[w*32 + g + 8*r];

#pragma unroll
        for (int ch = 0; ch < 4; ++ch) {
            int mb = ch*8;
            float u0 = us[mb+tg],   v0 = vs[mb+tg],   e0 = es[mb+tg];
            float u1 = us[mb+tg+4], v1 = vs[mb+tg+4], e1 = es[mb+tg+4];
            unsigned mk0 = 1u << (mb + tg);
            unsigned mk1 = mk0 << 4;
            unsigned A0[4], A1[4];
#pragma unroll
            for (int r = 0; r < 4; r++) {
                float p0 = (e0 >= nt[r]) ? Ae[r]*u0 : Be[r]*v0;
                p0 = (bwreg[r] & mk0) ? p0 : 0.f;
                unsigned q0 = to_tf32(p0);
                den[r] += __uint_as_float(q0);
                float p1 = (e1 >= nt[r]) ? Ae[r]*u1 : Be[r]*v1;
                p1 = (bwreg[r] & mk1) ? p1 : 0.f;
                unsigned q1 = to_tf32(p1);
                den[r] += __uint_as_float(q1);
                if (r < 2) { A0[(r&1)] = q0; A0[2 + (r&1)] = q1; }
                else       { A1[(r&1)] = q0; A1[2 + (r&1)] = q1; }
            }
            // conflict-free LDS.64 B-fragment loads
            const float2* bo = (const float2*)hs2 + ch*256 + lane;
#pragma unroll
            for (int o = 0; o < 8; o++) {
                float2 bq = bo[o*32];
                unsigned b0 = __float_as_uint(bq.x);
                unsigned b1 = __float_as_uint(bq.y);
                MMA_TF32(C[0][o], A0, b0, b1);
                MMA_TF32(C[1][o], A1, b0, b1);
            }
        }
    }

    // reduce denominators across the 4-lane k-group
#pragma unroll
    for (int r = 0; r < 4; r++) {
        den[r] += __shfl_xor_sync(0xffffffffu, den[r], 1);
        den[r] += __shfl_xor_sync(0xffffffffu, den[r], 2);
    }
    if (tg == 0) {
#pragma unroll
        for (int r = 0; r < 4; r++)
            g_pdn[((size_t)z*HH + hh)*NN + n0 + w*32 + g + 8*r] = den[r];
    }

    // write unnormalized partial numerators
    float* dst = g_pnm + ((size_t)z*NN + n0 + w*32)*HO + hh*OUTD;
#pragma unroll
    for (int tile = 0; tile < 2; tile++) {
        int rl = tile*16 + g;
        int rh = rl + 8;
#pragma unroll
        for (int o = 0; o < 8; o++) {
            int col = o*8 + 2*tg;
            *(float2*)&dst[(size_t)rl*HO + col] = make_float2(C[tile][o][0], C[tile][o][1]);
            *(float2*)&dst[(size_t)rh*HO + col] = make_float2(C[tile][o][2], C[tile][o][3]);
        }
    }
}

// ---------------- K3b: combine m-split partials ------------------------------
__global__ void k_combine() {     // grid NN, block 256
    int f = threadIdx.x;
    int n = blockIdx.x;
    float num = 0.f;
#pragma unroll
    for (int s = 0; s < MSPLIT; s++)
        num += g_pnm[((size_t)s*NN + n)*HO + f];
    int h = f >> 6;
    float den = 0.f;
#pragma unroll
    for (int s = 0; s < MSPLIT; s++)
        den += g_pdn[((size_t)s*HH + h)*NN + n];
    g_pre[(size_t)n*HO + f] = num / den;
}

// ---------------- K4: BN partial stats ---------------------------------------
__global__ void k_stats() {            // grid 256, block 256
    int f  = threadIdx.x;
    int b  = blockIdx.x;
    int r0 = b * 32;
    float s = 0.f, q = 0.f;
#pragma unroll 8
    for (int r = 0; r < 32; r++) {
        float vv = g_pre[(size_t)(r0 + r)*HO + f];
        s += vv;
        q += vv * vv;
    }
    g_psum[b*HO + f] = s;
    g_psq [b*HO + f] = q;
}

// ---------------- K5: finalize per-feature scale/shift ------------------------
__global__ void k_fin(const float* __restrict__ gamma,
                      const float* __restrict__ beta) {   // 1 block, 256 thr
    int f = threadIdx.x;
    float s = 0.f, q = 0.f;
    for (int k = 0; k < 256; k++) {
        s += g_psum[k*HO + f];
        q += g_psq [k*HO + f];
    }
    float mean = s * (1.0f / NN);
    float var  = q * (1.0f / NN) - mean * mean;
    float sc   = gamma[f] * rsqrtf(var + 1e-5f);
    g_scale[f] = sc;
    g_shift[f] = beta[f] - mean * sc;
}

// ---------------- K6: normalize + ReLU ----------------------------------------
__global__ void k_bn(float* __restrict__ out) {   // grid 8192, block 256
    int f = threadIdx.x;
    size_t idx = (size_t)blockIdx.x * HO + f;
    float v = g_pre[idx] * g_scale[f] + g_shift[f];
    out[idx] = v > 0.f ? v : 0.f;
}

// ---------------- launch -------------------------------------------------------
extern "C" void kernel_launch(void* const* d_in, const int* in_sizes, int n_in,
                              void* d_out, int out_size) {
    const float* x     = (const float*)d_in[0];   // [N, IN]
    const int*   adj   = (const int*)  d_in[1];   // [N, N]
    const float* W     = (const float*)d_in[2];   // [H, IN, OUT]
    const float* a_i   = (const float*)d_in[3];   // [H, OUT]
    const float* a_j   = (const float*)d_in[4];   // [H, OUT]
    const float* gamma = (const float*)d_in[5];   // [HO]
    const float* beta  = (const float*)d_in[6];   // [HO]
    float* out = (float*)d_out;                   // [N, HO]

    k_pack   <<< (NN/256)*NN, 256 >>>(adj);
    k_feat   <<< dim3(NN/32, HH), 256 >>>(x, W, a_i, a_j);
    k_gat_mma<<< dim3(NN/256, HH, MSPLIT), 256 >>>();
    k_combine<<< NN, 256 >>>();
    k_stats  <<< 256, 256 >>>();
    k_fin    <<< 1, 256 >>>(gamma, beta);
    k_bn     <<< NN, 256 >>>(out);
}

// round 13
// speedup vs baseline: 1.0297x; 1.0212x over previous
#include <cuda_runtime.h>

#define NN   8192
#define IND  128
#define OUTD 64
#define HH   4
#define HO   (HH*OUTD)   // 256
#define NW   (NN/32)     // 256 bitmask words per adjacency row
#define MSPLIT 8
#define MRANGE (NN/MSPLIT)   // 1024 m's per k_gat block
#define NTILES (MRANGE/32)   // 32 staged tiles per block

// ---------------- device scratch (static: no allocations allowed) ----------
__device__ float    g_h2[HH*NN*OUTD];       // 8 MB  h in MMA B-fragment order
__device__ unsigned g_bitsT[NW*NN];         // 8 MB  bit-packed adjacency (TRANSPOSED)
__device__ float    g_ei[HH*NN];
__device__ float    g_A [HH*NN];
__device__ float    g_B [HH*NN];
__device__ float    g_ej[HH*NN];
__device__ float    g_u [HH*NN];
__device__ float    g_v [HH*NN];
__device__ float    g_pnm[(size_t)MSPLIT*NN*HO];  // 64 MB partial numerators
__device__ float    g_pdn[MSPLIT*HH*NN];          // 1 MB  partial denominators
__device__ float    g_pre[NN*HO];
__device__ float    g_psum[256*HO];
__device__ float    g_psq [256*HO];
__device__ float    g_scale[HO];
__device__ float    g_shift[HO];

__device__ __forceinline__ unsigned to_tf32(float x) {
    unsigned q;
    asm("cvt.rna.tf32.f32 %0, %1;" : "=r"(q) : "f"(x));
    return q;
}

#define MMA_TF32(C, A, b0, b1)                                          \
    asm("mma.sync.aligned.m16n8k8.row.col.f32.tf32.tf32.f32 "           \
        "{%0,%1,%2,%3},{%4,%5,%6,%7},{%8,%9},{%0,%1,%2,%3};"            \
        : "+f"((C)[0]), "+f"((C)[1]), "+f"((C)[2]), "+f"((C)[3])        \
        : "r"((A)[0]), "r"((A)[1]), "r"((A)[2]), "r"((A)[3]),           \
          "r"(b0), "r"(b1))

#define CP16(dst, src) \
    asm volatile("cp.async.cg.shared.global [%0], [%1], 16;" :: "r"(dst), "l"(src))
#define CP4(dst, src) \
    asm volatile("cp.async.ca.shared.global [%0], [%1], 4;" :: "r"(dst), "l"(src))
#define CP_COMMIT() asm volatile("cp.async.commit_group;")
#define CP_WAIT(n)  asm volatile("cp.async.wait_group %0;" :: "n"(n))

// ---------------- K0: pack adjacency into TRANSPOSED bitmask ----------------
__global__ void k_pack(const int* __restrict__ adj) {
    int tid = blockIdx.x * 256 + threadIdx.x;   // tid = n*8192 + c
    int v = adj[tid];
    unsigned m = __ballot_sync(0xffffffffu, v != 0);
    if ((threadIdx.x & 31) == 0) {
        int n  = tid >> 13;
        int wd = (tid & (NN - 1)) >> 5;
        g_bitsT[(size_t)wd*NN + n] = m;
    }
}

// ---------------- K1: h = x @ W, fused scores/exp, fragment-order output ----
__global__ void __launch_bounds__(256) k_feat(const float* __restrict__ x,
                                              const float* __restrict__ W,
                                              const float* __restrict__ ai,
                                              const float* __restrict__ aj) {
    __shared__ float xs[32*IND];      // 16 KB
    __shared__ float Ws[IND*OUTD];    // 32 KB
    int h  = blockIdx.y;
    int n0 = blockIdx.x * 32;
    int t  = threadIdx.x;

    const float4* xsrc = (const float4*)(x + (size_t)n0 * IND);
    float4* xd = (float4*)xs;
#pragma unroll
    for (int k = 0; k < 4; k++) xd[t + k*256] = xsrc[t + k*256];
    const float4* wsrc = (const float4*)(W + (size_t)h * IND * OUTD);
    float4* wd = (float4*)Ws;
#pragma unroll
    for (int k = 0; k < 8; k++) wd[t + k*256] = wsrc[t + k*256];
    __syncthreads();

    int o2 = t & 31;
    int rg = t >> 5;
    float2 acc[4];
#pragma unroll
    for (int r = 0; r < 4; r++) { acc[r].x = 0.f; acc[r].y = 0.f; }

#pragma unroll 8
    for (int i = 0; i < IND; i++) {
        float2 wv = *(const float2*)&Ws[i*OUTD + o2*2];
#pragma unroll
        for (int r = 0; r < 4; r++) {
            float xv = xs[(rg*4 + r)*IND + i];
            acc[r].x += xv * wv.x;
            acc[r].y += xv * wv.y;
        }
    }

    float2 aiv = *(const float2*)&ai[h*OUTD + 2*o2];
    float2 ajv = *(const float2*)&aj[h*OUTD + 2*o2];
    float si[4], sj[4];
#pragma unroll
    for (int r = 0; r < 4; r++) {
        si[r] = acc[r].x*aiv.x + acc[r].y*aiv.y;
        sj[r] = acc[r].x*ajv.x + acc[r].y*ajv.y;
    }
#pragma unroll
    for (int off = 16; off; off >>= 1) {
#pragma unroll
        for (int r = 0; r < 4; r++) {
            si[r] += __shfl_xor_sync(0xffffffffu, si[r], off);
            sj[r] += __shfl_xor_sync(0xffffffffu, sj[r], off);
        }
    }
    if (o2 < 4) {
        float sI = (o2 == 0) ? si[0] : (o2 == 1) ? si[1] : (o2 == 2) ? si[2] : si[3];
        float sJ = (o2 == 0) ? sj[0] : (o2 == 1) ? sj[1] : (o2 == 2) ? sj[2] : sj[3];
        int idx = h*NN + n0 + rg*4 + o2;
        g_ei[idx] = sI;
        g_A [idx] = expf(sI);
        g_B [idx] = expf(0.2f * sI);
        g_ej[idx] = sJ;
        g_u [idx] = expf(sJ);
        g_v [idx] = expf(0.2f * sJ);
    }

    // store h in MMA B-fragment order (tf32-rounded)
    int hbase = h * (NN * OUTD);
#pragma unroll
    for (int r = 0; r < 4; r++) {
        int n    = n0 + rg*4 + r;
        int mm   = n & 31;
        int ch   = mm >> 3;
        int tg2  = mm & 3;
        int half = (mm >> 2) & 1;
        int c0   = 2*o2;
        int o    = c0 >> 3;
        int g    = c0 & 7;
        int idx  = ((ch<<3) + o)*64 + (g*4 + tg2)*2 + half;
        float* dst = g_h2 + hbase + (n >> 5)*2048 + idx;
        dst[0] = __uint_as_float(to_tf32(acc[r].x));
        dst[8] = __uint_as_float(to_tf32(acc[r].y));
    }
}

// ---------------- K3: tensor-core masked-softmax aggregation ----------------
// grid (NN/128, HH, MSPLIT), block 256 = 8 warps. Warp w -> 16 n-rows, 64 outs.
// Double-buffered cp.async staging of h / u / v / e / adjacency-word tiles.
__global__ void __launch_bounds__(256, 3) k_gat_mma() {
    __shared__ __align__(16) float    hs[2][2048];   // 16 KB
    __shared__ float    msc[2][96];                  // u[32] v[32] e[32] per stage
    __shared__ unsigned bwb[2][128];                 // adjacency words per stage

    int hh = blockIdx.y;
    int z  = blockIdx.z;
    int n0 = blockIdx.x * 128;
    int t  = threadIdx.x;
    int w    = t >> 5;
    int lane = t & 31;
    int g    = lane >> 2;
    int tg   = lane & 3;
    int mbase = z * MRANGE;

    float nt[2], Ae[2], Be[2];
    int rbase = hh*NN + n0 + w*16 + g;
#pragma unroll
    for (int r = 0; r < 2; r++) {
        nt[r] = -g_ei[rbase + 8*r];
        Ae[r] =  g_A [rbase + 8*r];
        Be[r] =  g_B [rbase + 8*r];
    }

    float C[8][4];
#pragma unroll
    for (int o = 0; o < 8; o++)
#pragma unroll
        for (int k = 0; k < 4; k++) C[o][k] = 0.f;
    float den[2] = {0.f, 0.f};

    const float* hsrc = g_h2 + (size_t)hh*NN*OUTD;
    unsigned hs_u  = (unsigned)__cvta_generic_to_shared(&hs[0][0]);
    unsigned msc_u = (unsigned)__cvta_generic_to_shared(&msc[0][0]);
    unsigned bw_u  = (unsigned)__cvta_generic_to_shared(&bwb[0][0]);

    // ---- prologue: prefetch tile 0 into buffer 0 ----
    {
        int m0s = mbase;
        const float4* src = (const float4*)(hsrc + (size_t)(m0s >> 5) * 2048);
        unsigned hd = hs_u + t*16;
        CP16(hd, src + t);
        CP16(hd + 4096, src + t + 256);
        if (t < 96) {
            const float* s = (t < 32) ? (g_u  + hh*NN + m0s + t)
                           : (t < 64) ? (g_v  + hh*NN + m0s + (t - 32))
                                      : (g_ej + hh*NN + m0s + (t - 64));
            CP4(msc_u + t*4, s);
        } else if (t < 224) {
            CP4(bw_u + (t - 96)*4, g_bitsT + (size_t)(m0s >> 5)*NN + n0 + (t - 96));
        }
    }
    CP_COMMIT();

    for (int sc = 0; sc < NTILES; ++sc) {
        // prefetch next tile (wrapped index on last iter: harmless reload)
        {
            int nb  = (sc + 1) & (NTILES - 1);
            int bf  = (sc + 1) & 1;
            int m0s = mbase + nb*32;
            const float4* src = (const float4*)(hsrc + (size_t)(m0s >> 5) * 2048);
            unsigned hd = hs_u + bf*8192 + t*16;
            CP16(hd, src + t);
            CP16(hd + 4096, src + t + 256);
            if (t < 96) {
                const float* s = (t < 32) ? (g_u  + hh*NN + m0s + t)
                               : (t < 64) ? (g_v  + hh*NN + m0s + (t - 32))
                                          : (g_ej + hh*NN + m0s + (t - 64));
                CP4(msc_u + bf*384 + t*4, s);
            } else if (t < 224) {
                CP4(bw_u + bf*512 + (t - 96)*4,
                    g_bitsT + (size_t)(m0s >> 5)*NN + n0 + (t - 96));
            }
        }
        CP_COMMIT();
        CP_WAIT(1);
        __syncthreads();

        int bf = sc & 1;
        unsigned bwreg0 = bwb[bf][w*16 + g];
        unsigned bwreg1 = bwb[bf][w*16 + g + 8];
        const float* uu = &msc[bf][0];
        const float* vv = &msc[bf][32];
        const float* ee = &msc[bf][64];

#pragma unroll
        for (int ch = 0; ch < 4; ++ch) {
            int mb = ch*8;
            float u0 = uu[mb+tg],   v0 = vv[mb+tg],   e0 = ee[mb+tg];
            float u1 = uu[mb+tg+4], v1 = vv[mb+tg+4], e1 = ee[mb+tg+4];
            unsigned mk0 = 1u << (mb + tg);
            unsigned mk1 = mk0 << 4;
            unsigned A0[4];
            {
                float p = (e0 >= nt[0]) ? Ae[0]*u0 : Be[0]*v0;
                p = (bwreg0 & mk0) ? p : 0.f;
                unsigned q = to_tf32(p); den[0] += __uint_as_float(q); A0[0] = q;
            }
            {
                float p = (e0 >= nt[1]) ? Ae[1]*u0 : Be[1]*v0;
                p = (bwreg1 & mk0) ? p : 0.f;
                unsigned q = to_tf32(p); den[1] += __uint_as_float(q); A0[1] = q;
            }
            {
                float p = (e1 >= nt[0]) ? Ae[0]*u1 : Be[0]*v1;
                p = (bwreg0 & mk1) ? p : 0.f;
                unsigned q = to_tf32(p); den[0] += __uint_as_float(q); A0[2] = q;
            }
            {
                float p = (e1 >= nt[1]) ? Ae[1]*u1 : Be[1]*v1;
                p = (bwreg1 & mk1) ? p : 0.f;
                unsigned q = to_tf32(p); den[1] += __uint_as_float(q); A0[3] = q;
            }
            const float2* bo = (const float2*)&hs[bf][0] + ch*256 + lane;
#pragma unroll
            for (int o = 0; o < 8; o++) {
                float2 bq = bo[o*32];
                MMA_TF32(C[o], A0, __float_as_uint(bq.x), __float_as_uint(bq.y));
            }
        }
        __syncthreads();
    }

    // reduce denominators across the 4-lane k-group
#pragma unroll
    for (int r = 0; r < 2; r++) {
        den[r] += __shfl_xor_sync(0xffffffffu, den[r], 1);
        den[r] += __shfl_xor_sync(0xffffffffu, den[r], 2);
    }
    if (tg == 0) {
        g_pdn[((size_t)z*HH + hh)*NN + n0 + w*16 + g]     = den[0];
        g_pdn[((size_t)z*HH + hh)*NN + n0 + w*16 + g + 8] = den[1];
    }

    // write unnormalized partial numerators
    float* dst = g_pnm + ((size_t)z*NN + n0 + w*16)*HO + hh*OUTD;
#pragma unroll
    for (int o = 0; o < 8; o++) {
        int col = o*8 + 2*tg;
        *(float2*)&dst[(size_t)g*HO + col]       = make_float2(C[o][0], C[o][1]);
        *(float2*)&dst[(size_t)(g + 8)*HO + col] = make_float2(C[o][2], C[o][3]);
    }
}

// ---------------- K3b: combine m-split partials + BN partial stats ----------
__global__ void k_combine() {     // grid 256, block 256; 32 rows/block
    int f = threadIdx.x;
    int b = blockIdx.x;
    int h = f >> 6;
    float s = 0.f, q = 0.f;
    for (int r = 0; r < 32; r++) {
        int n = b*32 + r;
        float num = 0.f, den = 0.f;
#pragma unroll
        for (int sp = 0; sp < MSPLIT; sp++) {
            num += g_pnm[((size_t)sp*NN + n)*HO + f];
            den += g_pdn[((size_t)sp*HH + h)*NN + n];
        }
        float val = num / den;
        g_pre[(size_t)n*HO + f] = val;
        s += val;
        q += val * val;
    }
    g_psum[b*HO + f] = s;
    g_psq [b*HO + f] = q;
}

// ---------------- K5: finalize per-feature scale/shift ------------------------
__global__ void k_fin(const float* __restrict__ gamma,
                      const float* __restrict__ beta) {   // 1 block, 256 thr
    int f = threadIdx.x;
    float s = 0.f, q = 0.f;
    for (int k = 0; k < 256; k++) {
        s += g_psum[k*HO + f];
        q += g_psq [k*HO + f];
    }
    float mean = s * (1.0f / NN);
    float var  = q * (1.0f / NN) - mean * mean;
    float sc   = gamma[f] * rsqrtf(var + 1e-5f);
    g_scale[f] = sc;
    g_shift[f] = beta[f] - mean * sc;
}

// ---------------- K6: normalize + ReLU ----------------------------------------
__global__ void k_bn(float* __restrict__ out) {   // grid 8192, block 256
    int f = threadIdx.x;
    size_t idx = (size_t)blockIdx.x * HO + f;
    float v = g_pre[idx] * g_scale[f] + g_shift[f];
    out[idx] = v > 0.f ? v : 0.f;
}

// ---------------- launch -------------------------------------------------------
extern "C" void kernel_launch(void* const* d_in, const int* in_sizes, int n_in,
                              void* d_out, int out_size) {
    const float* x     = (const float*)d_in[0];   // [N, IN]
    const int*   adj   = (const int*)  d_in[1];   // [N, N]
    const float* W     = (const float*)d_in[2];   // [H, IN, OUT]
    const float* a_i   = (const float*)d_in[3];   // [H, OUT]
    const float* a_j   = (const float*)d_in[4];   // [H, OUT]
    const float* gamma = (const float*)d_in[5];   // [HO]
    const float* beta  = (const float*)d_in[6];   // [HO]
    float* out = (float*)d_out;                   // [N, HO]

    k_pack   <<< (NN/256)*NN, 256 >>>(adj);
    k_feat   <<< dim3(NN/32, HH), 256 >>>(x, W, a_i, a_j);
    k_gat_mma<<< dim3(NN/128, HH, MSPLIT), 256 >>>();
    k_combine<<< 256, 256 >>>();
    k_fin    <<< 1, 256 >>>(gamma, beta);
    k_bn     <<< NN, 256 >>>(out);
}

// round 14
// speedup vs baseline: 1.0422x; 1.0121x over previous
#include <cuda_runtime.h>

#define NN   8192
#define IND  128
#define OUTD 64
#define HH   4
#define HO   (HH*OUTD)   // 256
#define NW   (NN/32)     // 256 bitmask words per adjacency row
#define MSPLIT 8
#define MRANGE (NN/MSPLIT)   // 1024 m's per k_gat block
#define NTILES (MRANGE/32)   // 32 staged tiles per block

// ---------------- device scratch (static: no allocations allowed) ----------
__device__ float    g_h2[HH*NN*OUTD];       // 8 MB  h in MMA B-fragment order
__device__ unsigned g_bitsT[NW*NN];         // 8 MB  bit-packed adjacency (TRANSPOSED)
__device__ float    g_ei[HH*NN];
__device__ float    g_A [HH*NN];
__device__ float    g_B [HH*NN];
__device__ float    g_ej[HH*NN];
__device__ float    g_u [HH*NN];
__device__ float    g_v [HH*NN];
__device__ float    g_pnm[(size_t)MSPLIT*NN*HO];  // 64 MB partial numerators
__device__ float    g_pdn[MSPLIT*HH*NN];          // 1 MB  partial denominators
__device__ float    g_pre[NN*HO];
__device__ float    g_psum[256*HO];
__device__ float    g_psq [256*HO];
__device__ float    g_scale[HO];
__device__ float    g_shift[HO];

__device__ __forceinline__ unsigned to_tf32(float x) {
    unsigned q;
    asm("cvt.rna.tf32.f32 %0, %1;" : "=r"(q) : "f"(x));
    return q;
}

#define MMA_TF32(C, A, b0, b1)                                          \
    asm("mma.sync.aligned.m16n8k8.row.col.f32.tf32.tf32.f32 "           \
        "{%0,%1,%2,%3},{%4,%5,%6,%7},{%8,%9},{%0,%1,%2,%3};"            \
        : "+f"((C)[0]), "+f"((C)[1]), "+f"((C)[2]), "+f"((C)[3])        \
        : "r"((A)[0]), "r"((A)[1]), "r"((A)[2]), "r"((A)[3]),           \
          "r"(b0), "r"(b1))

#define CP16(dst, src) \
    asm volatile("cp.async.cg.shared.global [%0], [%1], 16;" :: "r"(dst), "l"(src))
#define CP4(dst, src) \
    asm volatile("cp.async.ca.shared.global [%0], [%1], 4;" :: "r"(dst), "l"(src))
#define CP_COMMIT() asm volatile("cp.async.commit_group;")
#define CP_WAIT(n)  asm volatile("cp.async.wait_group %0;" :: "n"(n))

// ---------------- K0: pack adjacency into TRANSPOSED bitmask ----------------
__global__ void k_pack(const int* __restrict__ adj) {
    int tid = blockIdx.x * 256 + threadIdx.x;   // tid = n*8192 + c
    int v = adj[tid];
    unsigned m = __ballot_sync(0xffffffffu, v != 0);
    if ((threadIdx.x & 31) == 0) {
        int n  = tid >> 13;
        int wd = (tid & (NN - 1)) >> 5;
        g_bitsT[(size_t)wd*NN + n] = m;
    }
}

// ---------------- K1: h = x @ W, fused scores/exp, fragment-order output ----
__global__ void __launch_bounds__(256) k_feat(const float* __restrict__ x,
                                              const float* __restrict__ W,
                                              const float* __restrict__ ai,
                                              const float* __restrict__ aj) {
    __shared__ float xs[32*IND];      // 16 KB
    __shared__ float Ws[IND*OUTD];    // 32 KB
    int h  = blockIdx.y;
    int n0 = blockIdx.x * 32;
    int t  = threadIdx.x;

    const float4* xsrc = (const float4*)(x + (size_t)n0 * IND);
    float4* xd = (float4*)xs;
#pragma unroll
    for (int k = 0; k < 4; k++) xd[t + k*256] = xsrc[t + k*256];
    const float4* wsrc = (const float4*)(W + (size_t)h * IND * OUTD);
    float4* wd = (float4*)Ws;
#pragma unroll
    for (int k = 0; k < 8; k++) wd[t + k*256] = wsrc[t + k*256];
    __syncthreads();

    int o2 = t & 31;
    int rg = t >> 5;
    float2 acc[4];
#pragma unroll
    for (int r = 0; r < 4; r++) { acc[r].x = 0.f; acc[r].y = 0.f; }

#pragma unroll 8
    for (int i = 0; i < IND; i++) {
        float2 wv = *(const float2*)&Ws[i*OUTD + o2*2];
#pragma unroll
        for (int r = 0; r < 4; r++) {
            float xv = xs[(rg*4 + r)*IND + i];
            acc[r].x += xv * wv.x;
            acc[r].y += xv * wv.y;
        }
    }

    float2 aiv = *(const float2*)&ai[h*OUTD + 2*o2];
    float2 ajv = *(const float2*)&aj[h*OUTD + 2*o2];
    float si[4], sj[4];
#pragma unroll
    for (int r = 0; r < 4; r++) {
        si[r] = acc[r].x*aiv.x + acc[r].y*aiv.y;
        sj[r] = acc[r].x*ajv.x + acc[r].y*ajv.y;
    }
#pragma unroll
    for (int off = 16; off; off >>= 1) {
#pragma unroll
        for (int r = 0; r < 4; r++) {
            si[r] += __shfl_xor_sync(0xffffffffu, si[r], off);
            sj[r] += __shfl_xor_sync(0xffffffffu, sj[r], off);
        }
    }
    if (o2 < 4) {
        float sI = (o2 == 0) ? si[0] : (o2 == 1) ? si[1] : (o2 == 2) ? si[2] : si[3];
        float sJ = (o2 == 0) ? sj[0] : (o2 == 1) ? sj[1] : (o2 == 2) ? sj[2] : sj[3];
        int idx = h*NN + n0 + rg*4 + o2;
        g_ei[idx] = sI;
        g_A [idx] = expf(sI);
        g_B [idx] = expf(0.2f * sI);
        g_ej[idx] = sJ;
        g_u [idx] = expf(sJ);
        g_v [idx] = expf(0.2f * sJ);
    }

    // store h in MMA B-fragment order (tf32-rounded)
    int hbase = h * (NN * OUTD);
#pragma unroll
    for (int r = 0; r < 4; r++) {
        int n    = n0 + rg*4 + r;
        int mm   = n & 31;
        int ch   = mm >> 3;
        int tg2  = mm & 3;
        int half = (mm >> 2) & 1;
        int c0   = 2*o2;
        int o    = c0 >> 3;
        int g    = c0 & 7;
        int idx  = ((ch<<3) + o)*64 + (g*4 + tg2)*2 + half;
        float* dst = g_h2 + hbase + (n >> 5)*2048 + idx;
        dst[0] = __uint_as_float(to_tf32(acc[r].x));
        dst[8] = __uint_as_float(to_tf32(acc[r].y));
    }
}

// ---------------- K3: tensor-core masked-softmax aggregation ----------------
// grid (NN/128, HH, MSPLIT), block 256 = 8 warps. Warp w -> 16 n-rows, 64 outs.
// Double-buffered cp.async staging of h / u / v / e / adjacency-word tiles.
__global__ void __launch_bounds__(256, 3) k_gat_mma() {
    __shared__ __align__(16) float    hs[2][2048];   // 16 KB
    __shared__ float    msc[2][96];                  // u[32] v[32] e[32] per stage
    __shared__ unsigned bwb[2][128];                 // adjacency words per stage

    int hh = blockIdx.y;
    int z  = blockIdx.z;
    int n0 = blockIdx.x * 128;
    int t  = threadIdx.x;
    int w    = t >> 5;
    int lane = t & 31;
    int g    = lane >> 2;
    int tg   = lane & 3;
    int mbase = z * MRANGE;

    float nt[2], Ae[2], Be[2];
    int rbase = hh*NN + n0 + w*16 + g;
#pragma unroll
    for (int r = 0; r < 2; r++) {
        nt[r] = -g_ei[rbase + 8*r];
        Ae[r] =  g_A [rbase + 8*r];
        Be[r] =  g_B [rbase + 8*r];
    }

    float C[8][4];
#pragma unroll
    for (int o = 0; o < 8; o++)
#pragma unroll
        for (int k = 0; k < 4; k++) C[o][k] = 0.f;
    float den[2] = {0.f, 0.f};

    const float* hsrc = g_h2 + (size_t)hh*NN*OUTD;
    unsigned hs_u  = (unsigned)__cvta_generic_to_shared(&hs[0][0]);
    unsigned msc_u = (unsigned)__cvta_generic_to_shared(&msc[0][0]);
    unsigned bw_u  = (unsigned)__cvta_generic_to_shared(&bwb[0][0]);

    // ---- prologue: prefetch tile 0 into buffer 0 ----
    {
        int m0s = mbase;
        const float4* src = (const float4*)(hsrc + (size_t)(m0s >> 5) * 2048);
        unsigned hd = hs_u + t*16;
        CP16(hd, src + t);
        CP16(hd + 4096, src + t + 256);
        if (t < 96) {
            const float* s = (t < 32) ? (g_u  + hh*NN + m0s + t)
                           : (t < 64) ? (g_v  + hh*NN + m0s + (t - 32))
                                      : (g_ej + hh*NN + m0s + (t - 64));
            CP4(msc_u + t*4, s);
        } else if (t < 224) {
            CP4(bw_u + (t - 96)*4, g_bitsT + (size_t)(m0s >> 5)*NN + n0 + (t - 96));
        }
    }
    CP_COMMIT();

    for (int sc = 0; sc < NTILES; ++sc) {
        // prefetch next tile (wrapped index on last iter: harmless reload)
        {
            int nb  = (sc + 1) & (NTILES - 1);
            int bf  = (sc + 1) & 1;
            int m0s = mbase + nb*32;
            const float4* src = (const float4*)(hsrc + (size_t)(m0s >> 5) * 2048);
            unsigned hd = hs_u + bf*8192 + t*16;
            CP16(hd, src + t);
            CP16(hd + 4096, src + t + 256);
            if (t < 96) {
                const float* s = (t < 32) ? (g_u  + hh*NN + m0s + t)
                               : (t < 64) ? (g_v  + hh*NN + m0s + (t - 32))
                                          : (g_ej + hh*NN + m0s + (t - 64));
                CP4(msc_u + bf*384 + t*4, s);
            } else if (t < 224) {
                CP4(bw_u + bf*512 + (t - 96)*4,
                    g_bitsT + (size_t)(m0s >> 5)*NN + n0 + (t - 96));
            }
        }
        CP_COMMIT();
        CP_WAIT(1);
        __syncthreads();

        int bf = sc & 1;
        unsigned bwreg0 = bwb[bf][w*16 + g];
        unsigned bwreg1 = bwb[bf][w*16 + g + 8];
        const float* uu = &msc[bf][0];
        const float* vv = &msc[bf][32];
        const float* ee = &msc[bf][64];

#pragma unroll
        for (int ch = 0; ch < 4; ++ch) {
            int mb = ch*8;
            float u0 = uu[mb+tg],   v0 = vv[mb+tg],   e0 = ee[mb+tg];
            float u1 = uu[mb+tg+4], v1 = vv[mb+tg+4], e1 = ee[mb+tg+4];
            unsigned mk0 = 1u << (mb + tg);
            unsigned mk1 = mk0 << 4;
            unsigned A0[4];
            {
                float p = (e0 >= nt[0]) ? Ae[0]*u0 : Be[0]*v0;
                p = (bwreg0 & mk0) ? p : 0.f;
                unsigned q = to_tf32(p); den[0] += __uint_as_float(q); A0[0] = q;
            }
            {
                float p = (e0 >= nt[1]) ? Ae[1]*u0 : Be[1]*v0;
                p = (bwreg1 & mk0) ? p : 0.f;
                unsigned q = to_tf32(p); den[1] += __uint_as_float(q); A0[1] = q;
            }
            {
                float p = (e1 >= nt[0]) ? Ae[0]*u1 : Be[0]*v1;
                p = (bwreg0 & mk1) ? p : 0.f;
                unsigned q = to_tf32(p); den[0] += __uint_as_float(q); A0[2] = q;
            }
            {
                float p = (e1 >= nt[1]) ? Ae[1]*u1 : Be[1]*v1;
                p = (bwreg1 & mk1) ? p : 0.f;
                unsigned q = to_tf32(p); den[1] += __uint_as_float(q); A0[3] = q;
            }
            const float2* bo = (const float2*)&hs[bf][0] + ch*256 + lane;
#pragma unroll
            for (int o = 0; o < 8; o++) {
                float2 bq = bo[o*32];
                MMA_TF32(C[o], A0, __float_as_uint(bq.x), __float_as_uint(bq.y));
            }
        }
        __syncthreads();
    }

    // reduce denominators across the 4-lane k-group
#pragma unroll
    for (int r = 0; r < 2; r++) {
        den[r] += __shfl_xor_sync(0xffffffffu, den[r], 1);
        den[r] += __shfl_xor_sync(0xffffffffu, den[r], 2);
    }
    if (tg == 0) {
        g_pdn[((size_t)z*HH + hh)*NN + n0 + w*16 + g]     = den[0];
        g_pdn[((size_t)z*HH + hh)*NN + n0 + w*16 + g + 8] = den[1];
    }

    // write unnormalized partial numerators
    float* dst = g_pnm + ((size_t)z*NN + n0 + w*16)*HO + hh*OUTD;
#pragma unroll
    for (int o = 0; o < 8; o++) {
        int col = o*8 + 2*tg;
        *(float2*)&dst[(size_t)g*HO + col]       = make_float2(C[o][0], C[o][1]);
        *(float2*)&dst[(size_t)(g + 8)*HO + col] = make_float2(C[o][2], C[o][3]);
    }
}

// ---------------- K3b: combine m-split partials + BN partial stats ----------
__global__ void k_combine() {     // grid 256, block 256; 32 rows/block
    int f = threadIdx.x;
    int b = blockIdx.x;
    int h = f >> 6;
    float s = 0.f, q = 0.f;
    for (int r = 0; r < 32; r++) {
        int n = b*32 + r;
        float num = 0.f, den = 0.f;
#pragma unroll
        for (int sp = 0; sp < MSPLIT; sp++) {
            num += g_pnm[((size_t)sp*NN + n)*HO + f];
            den += g_pdn[((size_t)sp*HH + h)*NN + n];
        }
        float val = num / den;
        g_pre[(size_t)n*HO + f] = val;
        s += val;
        q += val * val;
    }
    g_psum[b*HO + f] = s;
    g_psq [b*HO + f] = q;
}

// ---------------- K5: finalize per-feature scale/shift ------------------------
__global__ void k_fin(const float* __restrict__ gamma,
                      const float* __restrict__ beta) {   // 1 block, 256 thr
    int f = threadIdx.x;
    float s = 0.f, q = 0.f;
    for (int k = 0; k < 256; k++) {
        s += g_psum[k*HO + f];
        q += g_psq [k*HO + f];
    }
    float mean = s * (1.0f / NN);
    float var  = q * (1.0f / NN) - mean * mean;
    float sc   = gamma[f] * rsqrtf(var + 1e-5f);
    g_scale[f] = sc;
    g_shift[f] = beta[f] - mean * sc;
}

// ---------------- K6: normalize + ReLU ----------------------------------------
__global__ void k_bn(float* __restrict__ out) {   // grid 8192, block 256
    int f = threadIdx.x;
    size_t idx = (size_t)blockIdx.x * HO + f;
    float v = g_pre[idx] * g_scale[f] + g_shift[f];
    out[idx] = v > 0.f ? v : 0.f;
}

// ---------------- launch -------------------------------------------------------
extern "C" void kernel_launch(void* const* d_in, const int* in_sizes, int n_in,
                              void* d_out, int out_size) {
    const float* x     = (const float*)d_in[0];   // [N, IN]
    const int*   adj   = (const int*)  d_in[1];   // [N, N]
    const float* W     = (const float*)d_in[2];   // [H, IN, OUT]
    const float* a_i   = (const float*)d_in[3];   // [H, OUT]
    const float* a_j   = (const float*)d_in[4];   // [H, OUT]
    const float* gamma = (const float*)d_in[5];   // [HO]
    const float* beta  = (const float*)d_in[6];   // [HO]
    float* out = (float*)d_out;                   // [N, HO]

    k_pack   <<< (NN/256)*NN, 256 >>>(adj);
    k_feat   <<< dim3(NN/32, HH), 256 >>>(x, W, a_i, a_j);
    k_gat_mma<<< dim3(NN/128, HH, MSPLIT), 256 >>>();
    k_combine<<< 256, 256 >>>();
    k_fin    <<< 1, 256 >>>(gamma, beta);
    k_bn     <<< NN, 256 >>>(out);
}